// round 10
// baseline (speedup 1.0000x reference)
#include <cuda_runtime.h>
#include <math.h>
#include <stdint.h>

#define BB 64
#define SS 1024
#define DD 512
#define NROWS (BB*SS)

#define NCH 32
#define SCHUNK (SS/NCH)

#define TPB 256
#define WPB (TPB/32)
#define RPW 4            // rows per warp (2 per iteration, one per half-warp)

#define EPS_F 1e-5f
#define MAXT 45.054565f  // asinh(sqrt(fp32_max))
#define FULL 0xffffffffu

__device__ __align__(16) float g_part[BB*NCH*DD];
__device__ __align__(16) float g_c1[BB*DD];
__device__ __align__(16) float g_mean[DD];

// ---------------------------------------------------------------------------
__device__ __forceinline__ float warp_sum(float v) {
    #pragma unroll
    for (int o = 16; o > 0; o >>= 1) v += __shfl_xor_sync(FULL, v, o);
    return v;
}

__device__ __forceinline__ float red512(float v) {
    __shared__ float sh[16];
    int w = threadIdx.x >> 5, l = threadIdx.x & 31;
    v = warp_sum(v);
    if (l == 0) sh[w] = v;
    __syncthreads();
    float r = 0.f;
    #pragma unroll
    for (int i = 0; i < 16; i++) r += sh[i];
    return r;
}

// non-hoistable 128-bit shared load
__device__ __forceinline__ float4 lds128v(uint32_t addr) {
    float4 v;
    asm volatile("ld.shared.v4.f32 {%0,%1,%2,%3}, [%4];"
                 : "=f"(v.x), "=f"(v.y), "=f"(v.z), "=f"(v.w) : "r"(addr));
    return v;
}

// K1a: per-(b,chunk) column partial sums over S, float4-vectorized
__global__ void __launch_bounds__(128) k_partial(const float* __restrict__ x) {
    int bc = blockIdx.x;            // b*NCH + c
    int t  = threadIdx.x;           // 0..127 -> float4 column t
    const float4* p = (const float4*)(x + (size_t)((bc / NCH) * SS + (bc % NCH) * SCHUNK) * DD) + t;
    float4 acc[8];
    #pragma unroll
    for (int j = 0; j < 8; j++) acc[j] = make_float4(0.f, 0.f, 0.f, 0.f);
    #pragma unroll
    for (int s = 0; s < SCHUNK; s += 8) {
        float4 v[8];
        #pragma unroll
        for (int j = 0; j < 8; j++) v[j] = p[(size_t)(s + j) * 128];
        #pragma unroll
        for (int j = 0; j < 8; j++) {
            acc[j].x += v[j].x; acc[j].y += v[j].y;
            acc[j].z += v[j].z; acc[j].w += v[j].w;
        }
    }
    float4 r;
    r.x = ((acc[0].x + acc[1].x) + (acc[2].x + acc[3].x)) + ((acc[4].x + acc[5].x) + (acc[6].x + acc[7].x));
    r.y = ((acc[0].y + acc[1].y) + (acc[2].y + acc[3].y)) + ((acc[4].y + acc[5].y) + (acc[6].y + acc[7].y));
    r.z = ((acc[0].z + acc[1].z) + (acc[2].z + acc[3].z)) + ((acc[4].z + acc[5].z) + (acc[6].z + acc[7].z));
    r.w = ((acc[0].w + acc[1].w) + (acc[2].w + acc[3].w)) + ((acc[4].w + acc[5].w) + (acc[6].w + acc[7].w));
    ((float4*)(g_part + (size_t)bc * DD))[t] = r;
}

// K1b: per-b centroid normalization
__global__ void k_c1() {
    int b = blockIdx.x, d = threadIdx.x;
    float a = 0.f;
    #pragma unroll
    for (int c = 0; c < NCH; c++) a += g_part[(size_t)(b * NCH + c) * DD + d];
    a *= (1.f / SS);
    float t = (d == 0) ? -a * a : a * a;
    float lin = red512(t);
    float denom = sqrtf(fmaxf(-lin, 1e-8f));
    g_c1[(size_t)b * DD + d] = a / denom;
}

// K1c: centroid over B
__global__ void k_mean() {
    int d = threadIdx.x;
    float a = 0.f;
    #pragma unroll 8
    for (int b = 0; b < BB; b++) a += g_c1[(size_t)b * DD + d];
    a *= (1.f / BB);
    float t = (d == 0) ? -a * a : a * a;
    float lin = red512(t);
    float denom = sqrtf(fmaxf(-lin, 1e-8f));
    g_mean[d] = a / denom;
}

// ---------------------------------------------------------------------------
// per-row scalar epilogue -> output coefficients (fast-math transcendentals)
__device__ __forceinline__ void row_coeffs(
    float sum, float ss, float exm, float exb, float x0,
    float g, float m0, float b0, float BmL, float Bc,
    float om0, float ob0, float Mss,
    float& c1, float& c2, float& c3, float& c4)
{
    const float lin  = exm - 2.f * x0 * m0;   // <mean,x>_L
    const float linb = exb - 2.f * x0 * b0;   // <beta,x>_L

    const float alpha = fmaxf(-lin, 1.f + 1e-7f);
    const float dnm   = sqrtf(alpha * alpha - 1.f);
    const float coef  = __fdividef(__logf(alpha + dnm), dnm);   // acosh(a)/sqrt(a^2-1)

    const float var  = (ss - sum * sum * (1.f / DD)) * (1.f / (DD - 1));
    const float sfac = g * rsqrtf(var) + EPS_F;

    const float v0 = coef * (x0 - alpha * m0);
    const float tf = -v0 * om0;
    const float A  = coef;
    const float C  = tf - coef * alpha;

    const float N  = sfac * sfac * (A*A*ss + C*C*Mss + tf*tf
                    + 2.f*A*C*exm + 2.f*A*tf*x0 + 2.f*C*tf*m0);
    const float w0 = sfac * (A * x0 + C * m0 + tf);
    const float L  = sfac * (A * linb + C * BmL - tf * b0);

    const float scale = fminf(1.f, MAXT * rsqrtf(fmaxf(N, 1e-8f)));
    const float f = scale * L * ob0;

    float n2 = scale*scale*(N - 2.f*w0*w0) + 2.f*scale*f*(L - w0) + f*f*Bc;
    n2 = fmaxf(n2, 1e-8f);
    const float n = sqrtf(n2);

    float chn, shn;
    if (n < 0.03f) {                      // series: rel err < 1e-7 here
        chn = 1.f + 0.5f * n2;
        shn = 1.f + n2 * (1.f / 6.f);
    } else {
        const float e  = __expf(n);
        const float ie = __fdividef(1.f, e);
        chn = 0.5f * (e + ie);
        shn = __fdividef(0.5f * (e - ie), n);
    }

    c1 = shn * (scale * sfac * A);
    c2 = shn * (scale * sfac * C);
    c3 = chn + shn * f;
    c4 = shn * (scale * sfac * tf + f);
}

// K2: half-warp per row — 16 lanes own one row (32 elems/lane).
// Butterfly only 4 levels; row_coeffs runs ONCE per warp (uniform per half).
__global__ void __launch_bounds__(TPB) k_main(const float* __restrict__ x,
                                              const float* __restrict__ beta,
                                              const float* __restrict__ gamma,
                                              float* __restrict__ out) {
    __shared__ __align__(16) float sm_m[DD];
    __shared__ __align__(16) float sm_b[DD];

    const int ln   = threadIdx.x & 31;
    const int wp   = threadIdx.x >> 5;
    const int half = ln >> 4;            // 0: row A, 1: row B
    const int hl   = ln & 15;            // lane within half

    {
        int t = threadIdx.x;
        float2 m2 = *(const float2*)(g_mean + t * 2);
        float2 b2 = *(const float2*)(beta   + t * 2);
        *(float2*)(sm_m + t * 2) = m2;
        *(float2*)(sm_b + t * 2) = b2;
    }
    const float g = gamma[0];
    __syncthreads();

    // per-lane smem base: chunk k covers cols [k*64, k*64+64); lane hl gets cols k*64+hl*4..+3
    const uint32_t smb_m = (uint32_t)__cvta_generic_to_shared(sm_m) + hl * 16;
    const uint32_t smb_b = (uint32_t)__cvta_generic_to_shared(sm_b) + hl * 16;

    // prologue constants (reduce within half: lanes of each half jointly cover all 512 cols)
    float Mss = 0.f, Bme = 0.f, Bsq = 0.f;
    #pragma unroll
    for (int k = 0; k < 8; k++) {
        float4 m4 = lds128v(smb_m + k * 256);
        float4 b4 = lds128v(smb_b + k * 256);
        Mss = fmaf(m4.x, m4.x, fmaf(m4.y, m4.y, fmaf(m4.z, m4.z, fmaf(m4.w, m4.w, Mss))));
        Bme = fmaf(b4.x, m4.x, fmaf(b4.y, m4.y, fmaf(b4.z, m4.z, fmaf(b4.w, m4.w, Bme))));
        Bsq = fmaf(b4.x, b4.x, fmaf(b4.y, b4.y, fmaf(b4.z, b4.z, fmaf(b4.w, b4.w, Bsq))));
    }
    #pragma unroll
    for (int o = 8; o > 0; o >>= 1) {
        Mss += __shfl_xor_sync(FULL, Mss, o);
        Bme += __shfl_xor_sync(FULL, Bme, o);
        Bsq += __shfl_xor_sync(FULL, Bsq, o);
    }

    const float m0  = sm_m[0];
    const float b0  = sm_b[0];
    const float BmL = Bme - 2.f * b0 * m0;
    const float Bc  = (Bsq - b0 * b0) - (1.f + b0) * (1.f + b0);
    const float om0 = 1.f / (1.f + m0);
    const float ob0 = 1.f / (1.f + b0);
    const bool  lead = (hl == 0);

    const size_t row0 = ((size_t)blockIdx.x * WPB + wp) * RPW;

    for (int i = 0; i < RPW; i += 2) {
        const size_t r = row0 + i + half;      // this half-warp's row
        const float4* px = (const float4*)(x + r * DD);

        // 8 float4 per lane; half-warp covers the row contiguously per chunk
        float xs[32];
        #pragma unroll
        for (int k = 0; k < 8; k++) {
            float4 v = px[k * 16 + hl];
            xs[k*4+0] = v.x; xs[k*4+1] = v.y; xs[k*4+2] = v.z; xs[k*4+3] = v.w;
        }

        // fused 4-way row sums
        float sum = 0.f, ss = 0.f, exm = 0.f, exb = 0.f;
        #pragma unroll
        for (int k = 0; k < 8; k++) {
            const float4 m4 = lds128v(smb_m + k * 256);
            const float4 b4 = lds128v(smb_b + k * 256);
            const float* a = xs + k * 4;
            sum += (a[0] + a[1]) + (a[2] + a[3]);
            ss  = fmaf(a[0], a[0], fmaf(a[1], a[1], fmaf(a[2], a[2], fmaf(a[3], a[3], ss))));
            exm = fmaf(a[0], m4.x, fmaf(a[1], m4.y, fmaf(a[2], m4.z, fmaf(a[3], m4.w, exm))));
            exb = fmaf(a[0], b4.x, fmaf(a[1], b4.y, fmaf(a[2], b4.z, fmaf(a[3], b4.w, exb))));
        }
        // 4-level butterfly within each 16-lane half
        #pragma unroll
        for (int o = 8; o > 0; o >>= 1) {
            sum += __shfl_xor_sync(FULL, sum, o);
            ss  += __shfl_xor_sync(FULL, ss,  o);
            exm += __shfl_xor_sync(FULL, exm, o);
            exb += __shfl_xor_sync(FULL, exb, o);
        }
        // x0 of this half's row lives in lane (half*16), element 0
        const float x0 = __shfl_sync(FULL, xs[0], half << 4);

        float c1, c2, c3, c4;
        row_coeffs(sum, ss, exm, exb, x0, g, m0, b0, BmL, Bc, om0, ob0, Mss,
                   c1, c2, c3, c4);

        float4* po = (float4*)(out + r * DD);
        #pragma unroll
        for (int k = 0; k < 8; k++) {
            const float4 m4 = lds128v(smb_m + k * 256);
            const float4 b4 = lds128v(smb_b + k * 256);
            float4 ov;
            ov.x = fmaf(c1, xs[k*4+0], fmaf(c2, m4.x, c3 * b4.x));
            ov.y = fmaf(c1, xs[k*4+1], fmaf(c2, m4.y, c3 * b4.y));
            ov.z = fmaf(c1, xs[k*4+2], fmaf(c2, m4.z, c3 * b4.z));
            ov.w = fmaf(c1, xs[k*4+3], fmaf(c2, m4.w, c3 * b4.w));
            if (k == 0 && lead) ov.x += c4;
            po[k * 16 + hl] = ov;
        }
    }
}

// ---------------------------------------------------------------------------
extern "C" void kernel_launch(void* const* d_in, const int* in_sizes, int n_in,
                              void* d_out, int out_size) {
    const float* x = nullptr;
    const float* beta = nullptr;
    const float* gamma = nullptr;
    for (int i = 0; i < n_in; i++) {
        if (in_sizes[i] == BB * SS * DD)      x = (const float*)d_in[i];
        else if (in_sizes[i] == DD)           beta = (const float*)d_in[i];
        else if (in_sizes[i] == 1)            gamma = (const float*)d_in[i];
    }
    float* out = (float*)d_out;

    k_partial<<<BB * NCH, 128>>>(x);
    k_c1<<<BB, DD>>>();
    k_mean<<<1, DD>>>();
    k_main<<<NROWS / (WPB * RPW), TPB>>>(x, beta, gamma, out);
}